// round 12
// baseline (speedup 1.0000x reference)
#include <cuda_runtime.h>
#include <cuda_bf16.h>
#include <cstdint>

// Problem constants
#define BB   2
#define LL   2048
#define SS   2048
#define DIN  512
#define DK   512
#define DV   512
#define DOUT 512
#define HH   8
#define HD   64

#define OUT_ELEMS  ((long)BB * LL * DOUT)
#define PROB_ELEMS ((long)BB * HH * (long)LL * (long)SS)

// Scratch (device globals — no runtime allocation allowed)
__device__ float g_q  [BB * LL * DK];
__device__ float g_k  [BB * SS * DK];
__device__ float g_v  [BB * SS * DV];
__device__ float g_cb [BB * HH * SS];
__device__ float g_ctx[BB * LL * DV];
__device__ float g_psum[BB * HH * (long)LL * 16];
__device__ float g_probs[BB * HH * (long)LL * SS];

// ---------------------------------------------------------------------------
// tf32 helpers (plain sm_103 target — mma.sync is the tensor path).
// f2tf32 = cvt.rna (round-to-nearest): UNBIASED, unlike the HW truncation the
// mma applies to raw fp32 — truncation's coherent -0.5ulp bias on both
// operands costs ~5e-4 systematic error on K=512 dot products (measured R10).
// ---------------------------------------------------------------------------
__device__ __forceinline__ float f2tf32(float v) {
    uint32_t r;
    asm("cvt.rna.tf32.f32 %0, %1;" : "=r"(r) : "f"(v));
    return __uint_as_float(r);
}

__device__ __forceinline__ void mma_tf32(float& c0, float& c1, float& c2, float& c3,
                                         float a0, float a1, float a2, float a3,
                                         float b0, float b1) {
    asm volatile(
        "mma.sync.aligned.m16n8k8.row.col.f32.tf32.tf32.f32 "
        "{%0,%1,%2,%3}, {%4,%5,%6,%7}, {%8,%9}, {%0,%1,%2,%3};"
        : "+f"(c0), "+f"(c1), "+f"(c2), "+f"(c3)
        : "r"(__float_as_uint(a0)), "r"(__float_as_uint(a1)),
          "r"(__float_as_uint(a2)), "r"(__float_as_uint(a3)),
          "r"(__float_as_uint(b0)), "r"(__float_as_uint(b1)));
}

#define CP_ASYNC16(dst_u32, src) \
    asm volatile("cp.async.cg.shared.global [%0], [%1], 16;" :: "r"(dst_u32), "l"(src))
#define CP_COMMIT() asm volatile("cp.async.commit_group;" ::: "memory")
#define CP_WAIT2()  asm volatile("cp.async.wait_group 2;" ::: "memory")

// ---------------------------------------------------------------------------
// Fused q/k/v projection: one launch, gridDim.z selects the GEMM.
//   z=0: q = queries @ Wq^T        z=1: k = keys @ Wk^T
//   z=2: v = values @ Wv^T + bv
// cp.async 3-stage, BK=32, XOR-swizzle, RNA-rounded fragments.
// grid = (N/128, M/128, 3), 256 threads, 96KB dynamic smem.
// ---------------------------------------------------------------------------
__global__ __launch_bounds__(256, 2)
void qkv_proj_kernel(const float* __restrict__ q_in,
                     const float* __restrict__ k_in,
                     const float* __restrict__ v_in,
                     const float* __restrict__ Wq,
                     const float* __restrict__ Wk,
                     const float* __restrict__ Wv,
                     const float* __restrict__ bv,
                     float* __restrict__ q_out,
                     float* __restrict__ k_out,
                     float* __restrict__ v_out) {
    extern __shared__ float sm[];
    __shared__ float bias_s[128];

    const int tid  = threadIdx.x;
    const int wid  = tid >> 5;
    const int lane = tid & 31;
    const int warp_m = wid >> 2;
    const int warp_n = wid & 3;

    const int zz = blockIdx.z;
    const int bm = blockIdx.y * 128;
    const int bn = blockIdx.x * 128;
    const int K  = DIN, N = DK;

    const float* A; const float* W; float* C; bool hasb = false;
    if (zz == 0)      { A = q_in; W = Wq; C = q_out; }
    else if (zz == 1) { A = k_in; W = Wk; C = k_out; }
    else              { A = v_in; W = Wv; C = v_out; hasb = true; }

    const float* Ag = A + (size_t)bm * K;
    const float* Wg = W + (size_t)bn * K;

    if (tid < 128) bias_s[tid] = hasb ? bv[bn + tid] : 0.0f;

    const uint32_t sbase = (uint32_t)__cvta_generic_to_shared(sm);

    auto issue = [&](int cidx) {
        const uint32_t st_off = (uint32_t)(cidx % 3) * 8192u * 4u;
        const int kc = cidx * 32;
        #pragma unroll
        for (int i = 0; i < 4; i++) {
            int idx = tid + i * 256;
            int r   = idx >> 3;
            int gcf = (idx & 7) * 4;
            int sc  = gcf ^ ((r & 7) << 2);
            uint32_t da = sbase + st_off + (uint32_t)(r * 32 + sc) * 4u;
            CP_ASYNC16(da,          Ag + (size_t)r * K + kc + gcf);
            CP_ASYNC16(da + 16384u, Wg + (size_t)r * K + kc + gcf);
        }
    };

    float acc[4][4][4];
    #pragma unroll
    for (int i = 0; i < 4; i++)
        #pragma unroll
        for (int j = 0; j < 4; j++)
            #pragma unroll
            for (int t = 0; t < 4; t++) acc[i][j][t] = 0.0f;

    const int NC = K / 32;
    issue(0); CP_COMMIT();
    issue(1); CP_COMMIT();
    __syncthreads();   // bias_s visible

    const int ar = lane >> 2;
    const int ac = lane & 3;

    for (int c = 0; c < NC; c++) {
        if (c + 2 < NC) issue(c + 2);
        CP_COMMIT();
        CP_WAIT2();
        __syncthreads();

        const float* As = sm + (c % 3) * 8192;
        const float* Bs = As + 4096;

        #pragma unroll
        for (int kk = 0; kk < 4; kk++) {
            const int k0 = kk * 8;
            const int sc0 = (k0 + ac)     ^ (ar << 2);
            const int sc1 = (k0 + ac + 4) ^ (ar << 2);
            float a0[4], a1[4], a2[4], a3[4];
            #pragma unroll
            for (int i = 0; i < 4; i++) {
                int m = warp_m * 64 + i * 16;
                a0[i] = f2tf32(As[(m + ar    ) * 32 + sc0]);
                a1[i] = f2tf32(As[(m + ar + 8) * 32 + sc0]);
                a2[i] = f2tf32(As[(m + ar    ) * 32 + sc1]);
                a3[i] = f2tf32(As[(m + ar + 8) * 32 + sc1]);
            }
            float b0[4], b1[4];
            #pragma unroll
            for (int j = 0; j < 4; j++) {
                int n = warp_n * 32 + j * 8 + ar;
                b0[j] = f2tf32(Bs[n * 32 + sc0]);
                b1[j] = f2tf32(Bs[n * 32 + sc1]);
            }
            #pragma unroll
            for (int i = 0; i < 4; i++)
                #pragma unroll
                for (int j = 0; j < 4; j++)
                    mma_tf32(acc[i][j][0], acc[i][j][1], acc[i][j][2], acc[i][j][3],
                             a0[i], a1[i], a2[i], a3[i], b0[j], b1[j]);
        }
        __syncthreads();
    }

    #pragma unroll
    for (int i = 0; i < 4; i++) {
        int row = bm + warp_m * 64 + i * 16 + ar;
        #pragma unroll
        for (int j = 0; j < 4; j++) {
            int col = warp_n * 32 + j * 8 + ac * 2;
            float bb0 = bias_s[col], bb1 = bias_s[col + 1];
            float2 v0, v1;
            v0.x = acc[i][j][0] + bb0; v0.y = acc[i][j][1] + bb1;
            v1.x = acc[i][j][2] + bb0; v1.y = acc[i][j][3] + bb1;
            *(float2*)(C + (size_t)row * N + bn + col) = v0;
            *(float2*)(C + (size_t)(row + 8) * N + bn + col) = v1;
        }
    }
}

// ---------------------------------------------------------------------------
// Pipelined tf32 GEMM (output projection): C = A @ W^T + bias.
// RNA-rounded fragments. grid = (N/128, M/128), 96KB dynamic smem.
// ---------------------------------------------------------------------------
__global__ __launch_bounds__(256, 2)
void gemm_cp_kernel(const float* __restrict__ A,
                    const float* __restrict__ W,
                    const float* __restrict__ bias,
                    float* __restrict__ C,
                    int M, int N, int K) {
    extern __shared__ float sm[];
    __shared__ float bias_s[128];

    const int tid  = threadIdx.x;
    const int wid  = tid >> 5;
    const int lane = tid & 31;
    const int warp_m = wid >> 2;
    const int warp_n = wid & 3;

    const int bm = blockIdx.y * 128;
    const int bn = blockIdx.x * 128;

    const float* Ag = A + (size_t)bm * K;
    const float* Wg = W + (size_t)bn * K;

    if (tid < 128) bias_s[tid] = bias[bn + tid];

    const uint32_t sbase = (uint32_t)__cvta_generic_to_shared(sm);

    auto issue = [&](int cidx) {
        const uint32_t st_off = (uint32_t)(cidx % 3) * 8192u * 4u;
        const int kc = cidx * 32;
        #pragma unroll
        for (int i = 0; i < 4; i++) {
            int idx = tid + i * 256;
            int r   = idx >> 3;
            int gcf = (idx & 7) * 4;
            int sc  = gcf ^ ((r & 7) << 2);
            uint32_t da = sbase + st_off + (uint32_t)(r * 32 + sc) * 4u;
            CP_ASYNC16(da,          Ag + (size_t)r * K + kc + gcf);
            CP_ASYNC16(da + 16384u, Wg + (size_t)r * K + kc + gcf);
        }
    };

    float acc[4][4][4];
    #pragma unroll
    for (int i = 0; i < 4; i++)
        #pragma unroll
        for (int j = 0; j < 4; j++)
            #pragma unroll
            for (int t = 0; t < 4; t++) acc[i][j][t] = 0.0f;

    const int NC = K / 32;
    issue(0); CP_COMMIT();
    issue(1); CP_COMMIT();
    __syncthreads();

    const int ar = lane >> 2;
    const int ac = lane & 3;

    for (int c = 0; c < NC; c++) {
        if (c + 2 < NC) issue(c + 2);
        CP_COMMIT();
        CP_WAIT2();
        __syncthreads();

        const float* As = sm + (c % 3) * 8192;
        const float* Bs = As + 4096;

        #pragma unroll
        for (int kk = 0; kk < 4; kk++) {
            const int k0 = kk * 8;
            const int sc0 = (k0 + ac)     ^ (ar << 2);
            const int sc1 = (k0 + ac + 4) ^ (ar << 2);
            float a0[4], a1[4], a2[4], a3[4];
            #pragma unroll
            for (int i = 0; i < 4; i++) {
                int m = warp_m * 64 + i * 16;
                a0[i] = f2tf32(As[(m + ar    ) * 32 + sc0]);
                a1[i] = f2tf32(As[(m + ar + 8) * 32 + sc0]);
                a2[i] = f2tf32(As[(m + ar    ) * 32 + sc1]);
                a3[i] = f2tf32(As[(m + ar + 8) * 32 + sc1]);
            }
            float b0[4], b1[4];
            #pragma unroll
            for (int j = 0; j < 4; j++) {
                int n = warp_n * 32 + j * 8 + ar;
                b0[j] = f2tf32(Bs[n * 32 + sc0]);
                b1[j] = f2tf32(Bs[n * 32 + sc1]);
            }
            #pragma unroll
            for (int i = 0; i < 4; i++)
                #pragma unroll
                for (int j = 0; j < 4; j++)
                    mma_tf32(acc[i][j][0], acc[i][j][1], acc[i][j][2], acc[i][j][3],
                             a0[i], a1[i], a2[i], a3[i], b0[j], b1[j]);
        }
        __syncthreads();
    }

    #pragma unroll
    for (int i = 0; i < 4; i++) {
        int row = bm + warp_m * 64 + i * 16 + ar;
        #pragma unroll
        for (int j = 0; j < 4; j++) {
            int col = warp_n * 32 + j * 8 + ac * 2;
            float bb0 = bias_s[col], bb1 = bias_s[col + 1];
            float2 v0, v1;
            v0.x = acc[i][j][0] + bb0; v0.y = acc[i][j][1] + bb1;
            v1.x = acc[i][j][2] + bb0; v1.y = acc[i][j][3] + bb1;
            *(float2*)(C + (size_t)row * N + bn + col) = v0;
            *(float2*)(C + (size_t)(row + 8) * N + bn + col) = v1;
        }
    }
}

// ---------------------------------------------------------------------------
// Scores: tf32 GEMM, cp.async 3-stage, BK=32; mixing folded into A-fragment
// loads (fp32 product, RNA-rounded to tf32 — unbiased):
//   e[z,l,s] = exp((sum_k q[l,k]*mix[h,k]*kmat[s,k] + cb[z,s]) / 8) -> probs
//   psum[z,l,cta_n] = partial row sums (deterministic)
// ---------------------------------------------------------------------------
__global__ __launch_bounds__(256, 2)
void scores_mma_kernel(const float* __restrict__ q,
                       const float* __restrict__ kmat,
                       const float* __restrict__ mixing,
                       const float* __restrict__ cb,
                       float* __restrict__ probs,
                       float* __restrict__ psum) {
    extern __shared__ float sm[];
    __shared__ float mix_s[DK];
    __shared__ float cb_s[128];
    __shared__ float rs[4][130];

    const int tid  = threadIdx.x;
    const int wid  = tid >> 5;
    const int lane = tid & 31;
    const int warp_m = wid >> 2;
    const int warp_n = wid & 3;

    const int z  = blockIdx.z;
    const int b  = z >> 3;
    const int h  = z & 7;
    const int bm = blockIdx.y * 128;
    const int bn = blockIdx.x * 128;

    const float* Aq = q    + (size_t)b * LL * DK + (size_t)bm * DK;
    const float* Bk = kmat + (size_t)b * SS * DK + (size_t)bn * DK;

    for (int i = tid; i < DK; i += 256) mix_s[i] = mixing[h * DK + i];
    if (tid < 128) cb_s[tid] = cb[(size_t)z * SS + bn + tid];

    const uint32_t sbase = (uint32_t)__cvta_generic_to_shared(sm);

    auto issue = [&](int cidx) {
        const uint32_t st_off = (uint32_t)(cidx % 3) * 8192u * 4u;
        const int kc = cidx * 32;
        #pragma unroll
        for (int i = 0; i < 4; i++) {
            int idx = tid + i * 256;
            int r   = idx >> 3;
            int gcf = (idx & 7) * 4;
            int sc  = gcf ^ ((r & 7) << 2);
            uint32_t da = sbase + st_off + (uint32_t)(r * 32 + sc) * 4u;
            CP_ASYNC16(da,          Aq + (size_t)r * DK + kc + gcf);
            CP_ASYNC16(da + 16384u, Bk + (size_t)r * DK + kc + gcf);
        }
    };

    float acc[4][4][4];
    #pragma unroll
    for (int i = 0; i < 4; i++)
        #pragma unroll
        for (int j = 0; j < 4; j++)
            #pragma unroll
            for (int t = 0; t < 4; t++) acc[i][j][t] = 0.0f;

    const int NC = DK / 32;
    issue(0); CP_COMMIT();
    issue(1); CP_COMMIT();
    __syncthreads();   // mix_s/cb_s visible before mainloop fragment use

    const int ar = lane >> 2;
    const int ac = lane & 3;

    for (int c = 0; c < NC; c++) {
        if (c + 2 < NC) issue(c + 2);
        CP_COMMIT();
        CP_WAIT2();
        __syncthreads();

        const float* As = sm + (c % 3) * 8192;
        const float* Bs = As + 4096;
        const int kc = c * 32;

        #pragma unroll
        for (int kk = 0; kk < 4; kk++) {
            const int k0 = kk * 8;
            const int sc0 = (k0 + ac)     ^ (ar << 2);
            const int sc1 = (k0 + ac + 4) ^ (ar << 2);
            const float mv0 = mix_s[kc + k0 + ac];
            const float mv1 = mix_s[kc + k0 + ac + 4];
            float a0[4], a1[4], a2[4], a3[4];
            #pragma unroll
            for (int i = 0; i < 4; i++) {
                int m = warp_m * 64 + i * 16;
                a0[i] = f2tf32(As[(m + ar    ) * 32 + sc0] * mv0);
                a1[i] = f2tf32(As[(m + ar + 8) * 32 + sc0] * mv0);
                a2[i] = f2tf32(As[(m + ar    ) * 32 + sc1] * mv1);
                a3[i] = f2tf32(As[(m + ar + 8) * 32 + sc1] * mv1);
            }
            float b0[4], b1[4];
            #pragma unroll
            for (int j = 0; j < 4; j++) {
                int n = warp_n * 32 + j * 8 + ar;
                b0[j] = f2tf32(Bs[n * 32 + sc0]);
                b1[j] = f2tf32(Bs[n * 32 + sc1]);
            }
            #pragma unroll
            for (int i = 0; i < 4; i++)
                #pragma unroll
                for (int j = 0; j < 4; j++)
                    mma_tf32(acc[i][j][0], acc[i][j][1], acc[i][j][2], acc[i][j][3],
                             a0[i], a1[i], a2[i], a3[i], b0[j], b1[j]);
        }
        __syncthreads();
    }

    const size_t rowbase = (size_t)z * LL;
    float rsum[4][2];
    #pragma unroll
    for (int i = 0; i < 4; i++) { rsum[i][0] = 0.0f; rsum[i][1] = 0.0f; }

    #pragma unroll
    for (int i = 0; i < 4; i++) {
        int row = bm + warp_m * 64 + i * 16 + ar;
        #pragma unroll
        for (int j = 0; j < 4; j++) {
            int col = warp_n * 32 + j * 8 + ac * 2;
            float cb0 = cb_s[col], cb1 = cb_s[col + 1];
            float2 v0, v1;
            v0.x = __expf((acc[i][j][0] + cb0) * 0.125f);
            v0.y = __expf((acc[i][j][1] + cb1) * 0.125f);
            v1.x = __expf((acc[i][j][2] + cb0) * 0.125f);
            v1.y = __expf((acc[i][j][3] + cb1) * 0.125f);
            rsum[i][0] += v0.x + v0.y;
            rsum[i][1] += v1.x + v1.y;
            __stcs((float2*)(probs + (rowbase + row    ) * SS + bn + col), v0);
            __stcs((float2*)(probs + (rowbase + row + 8) * SS + bn + col), v1);
        }
    }
    #pragma unroll
    for (int i = 0; i < 4; i++) {
        rsum[i][0] += __shfl_xor_sync(0xffffffffu, rsum[i][0], 1);
        rsum[i][0] += __shfl_xor_sync(0xffffffffu, rsum[i][0], 2);
        rsum[i][1] += __shfl_xor_sync(0xffffffffu, rsum[i][1], 1);
        rsum[i][1] += __shfl_xor_sync(0xffffffffu, rsum[i][1], 2);
    }
    if ((lane & 3) == 0) {
        #pragma unroll
        for (int i = 0; i < 4; i++) {
            int r = warp_m * 64 + i * 16 + ar;
            rs[warp_n][r]     = rsum[i][0];
            rs[warp_n][r + 8] = rsum[i][1];
        }
    }
    __syncthreads();
    if (tid < 128) {
        float s = rs[0][tid] + rs[1][tid] + rs[2][tid] + rs[3][tid];
        psum[(rowbase + bm + tid) * 16 + blockIdx.x] = s;
    }
}

// ---------------------------------------------------------------------------
// ctx via tf32 mma, cp.async 3-stage, BK=32, fused normalization;
// RNA-rounded fragments.
// ---------------------------------------------------------------------------
#define CTX_STAGE 6400

__global__ __launch_bounds__(256, 2)
void ctx_mma_kernel(float* __restrict__ probs,
                    const float* __restrict__ psum,
                    const float* __restrict__ v,
                    float* __restrict__ ctx) {
    extern __shared__ float sm[];
    __shared__ float invs[128];

    const int tid  = threadIdx.x;
    const int wid  = tid >> 5;
    const int lane = tid & 31;
    const int warp_m = wid >> 2;
    const int warp_n = wid & 3;

    const int z  = blockIdx.y;
    const int b  = z >> 3;
    const int h  = z & 7;
    const int bm = blockIdx.x * 128;

    float* P = probs + ((size_t)z * LL + bm) * SS;
    const float* V = v + (size_t)b * SS * DV + h * HD;

    if (tid < 128) {
        const float* pp = psum + ((size_t)z * LL + bm + tid) * 16;
        float4 s0 = *(const float4*)(pp + 0);
        float4 s1 = *(const float4*)(pp + 4);
        float4 s2 = *(const float4*)(pp + 8);
        float4 s3 = *(const float4*)(pp + 12);
        float s = ((s0.x + s0.y) + (s0.z + s0.w)) + ((s1.x + s1.y) + (s1.z + s1.w))
                + ((s2.x + s2.y) + (s2.z + s2.w)) + ((s3.x + s3.y) + (s3.z + s3.w));
        invs[tid] = 1.0f / s;
    }
    __syncthreads();

    const uint32_t sbase = (uint32_t)__cvta_generic_to_shared(sm);

    auto issue = [&](int cidx) {
        const uint32_t st = (uint32_t)(cidx % 3) * (CTX_STAGE * 4u);
        const int kc = cidx * 32;
        #pragma unroll
        for (int i = 0; i < 4; i++) {
            int idx = tid + i * 256;
            int r   = idx >> 3;
            int gcf = (idx & 7) * 4;
            int sc  = gcf ^ ((r & 7) << 2);
            CP_ASYNC16(sbase + st + (uint32_t)(r * 32 + sc) * 4u,
                       P + (size_t)r * SS + kc + gcf);
        }
        #pragma unroll
        for (int i = 0; i < 2; i++) {
            int idx = tid + i * 256;
            int vr  = idx >> 4;
            int vc  = (idx & 15) * 4;
            CP_ASYNC16(sbase + st + (uint32_t)(4096 + vr * 72 + vc) * 4u,
                       V + (size_t)(kc + vr) * DV + vc);
        }
    };

    const int ar = lane >> 2;
    const int ac = lane & 3;

    float ivA[8];
    #pragma unroll
    for (int i = 0; i < 4; i++) {
        ivA[2 * i]     = invs[warp_m * 64 + i * 16 + ar];
        ivA[2 * i + 1] = invs[warp_m * 64 + i * 16 + ar + 8];
    }
    float ivW[4];
    #pragma unroll
    for (int i = 0; i < 4; i++) ivW[i] = invs[(tid + i * 256) >> 3];

    float acc[4][2][4];
    #pragma unroll
    for (int i = 0; i < 4; i++)
        #pragma unroll
        for (int j = 0; j < 2; j++)
            #pragma unroll
            for (int t = 0; t < 4; t++) acc[i][j][t] = 0.0f;

    const int NC = SS / 32;
    issue(0); CP_COMMIT();
    issue(1); CP_COMMIT();

    for (int c = 0; c < NC; c++) {
        if (c + 2 < NC) issue(c + 2);
        CP_COMMIT();
        CP_WAIT2();
        __syncthreads();

        const float* Ps = sm + (c % 3) * CTX_STAGE;
        const float* Vs = Ps + 4096;
        const int kc = c * 32;

        #pragma unroll
        for (int i = 0; i < 4; i++) {
            int idx = tid + i * 256;
            int r   = idx >> 3;
            int gcf = (idx & 7) * 4;
            int sc  = gcf ^ ((r & 7) << 2);
            float4 e = *(const float4*)&Ps[r * 32 + sc];
            float iv = ivW[i];
            float4 nv = make_float4(e.x * iv, e.y * iv, e.z * iv, e.w * iv);
            __stcs((float4*)(P + (size_t)r * SS + kc + gcf), nv);
        }

        #pragma unroll
        for (int kk = 0; kk < 4; kk++) {
            const int k0 = kk * 8;
            const int sc0 = (k0 + ac)     ^ (ar << 2);
            const int sc1 = (k0 + ac + 4) ^ (ar << 2);
            float a0[4], a1[4], a2[4], a3[4];
            #pragma unroll
            for (int i = 0; i < 4; i++) {
                int m = warp_m * 64 + i * 16;
                a0[i] = f2tf32(Ps[(m + ar    ) * 32 + sc0] * ivA[2 * i]);
                a1[i] = f2tf32(Ps[(m + ar + 8) * 32 + sc0] * ivA[2 * i + 1]);
                a2[i] = f2tf32(Ps[(m + ar    ) * 32 + sc1] * ivA[2 * i]);
                a3[i] = f2tf32(Ps[(m + ar + 8) * 32 + sc1] * ivA[2 * i + 1]);
            }
            float b0[2], b1[2];
            #pragma unroll
            for (int j = 0; j < 2; j++) {
                int n = warp_n * 16 + j * 8 + ar;
                b0[j] = f2tf32(Vs[(k0 + ac) * 72 + n]);
                b1[j] = f2tf32(Vs[(k0 + ac + 4) * 72 + n]);
            }
            #pragma unroll
            for (int i = 0; i < 4; i++)
                #pragma unroll
                for (int j = 0; j < 2; j++)
                    mma_tf32(acc[i][j][0], acc[i][j][1], acc[i][j][2], acc[i][j][3],
                             a0[i], a1[i], a2[i], a3[i], b0[j], b1[j]);
        }
        __syncthreads();
    }

    #pragma unroll
    for (int i = 0; i < 4; i++) {
        int row = bm + warp_m * 64 + i * 16 + ar;
        #pragma unroll
        for (int j = 0; j < 2; j++) {
            int col = warp_n * 16 + j * 8 + ac * 2;
            float2 v0, v1;
            v0.x = acc[i][j][0]; v0.y = acc[i][j][1];
            v1.x = acc[i][j][2]; v1.y = acc[i][j][3];
            *(float2*)(ctx + (size_t)(b * LL + row) * DV + h * HD + col) = v0;
            *(float2*)(ctx + (size_t)(b * LL + row + 8) * DV + h * HD + col) = v1;
        }
    }
}

// ---------------------------------------------------------------------------
// cb kernel (unchanged)
// ---------------------------------------------------------------------------
__global__ void cb_kernel(const float* __restrict__ keys,
                          const float* __restrict__ Wcb,
                          float* __restrict__ cb) {
    const int bs = blockIdx.x;
    const int b  = bs / SS;
    const int s  = bs % SS;
    __shared__ float krow[DIN];
    const int tid = threadIdx.x;
    for (int i = tid; i < DIN; i += 256) krow[i] = keys[(size_t)bs * DIN + i];
    __syncthreads();
    const int w    = tid >> 5;
    const int lane = tid & 31;
    float sum = 0.0f;
    #pragma unroll 4
    for (int i = lane; i < DIN; i += 32) sum += krow[i] * Wcb[w * DIN + i];
    #pragma unroll
    for (int o = 16; o > 0; o >>= 1) sum += __shfl_down_sync(0xffffffffu, sum, o);
    if (lane == 0) cb[(size_t)(b * HH + w) * SS + s] = sum;
}

// ---------------------------------------------------------------------------
extern "C" void kernel_launch(void* const* d_in, const int* in_sizes, int n_in,
                              void* d_out, int out_size) {
    const float* queries = (const float*)d_in[0];
    const float* keys    = (const float*)d_in[1];
    const float* values  = (const float*)d_in[2];
    const float* Wq      = (const float*)d_in[4];
    const float* Wk      = (const float*)d_in[5];
    const float* Wv      = (const float*)d_in[6];
    const float* bv      = (const float*)d_in[7];
    const float* Wcb     = (const float*)d_in[8];
    const float* mixing  = (const float*)d_in[9];
    const float* Wd      = (const float*)d_in[10];
    const float* bd      = (const float*)d_in[11];

    float* out = (float*)d_out;

    void *pq, *pk, *pv, *pcb, *pctx, *ppsum, *pprobs;
    cudaGetSymbolAddress(&pq,    g_q);
    cudaGetSymbolAddress(&pk,    g_k);
    cudaGetSymbolAddress(&pv,    g_v);
    cudaGetSymbolAddress(&pcb,   g_cb);
    cudaGetSymbolAddress(&pctx,  g_ctx);
    cudaGetSymbolAddress(&ppsum, g_psum);
    cudaGetSymbolAddress(&pprobs, g_probs);

    float* probs;
    if ((long)out_size >= OUT_ELEMS + PROB_ELEMS) probs = out + OUT_ELEMS;
    else                                           probs = (float*)pprobs;

    const int SC_SMEM  = 3 * 8192 * 4;        // 96 KB
    const int CTX_SMEM = 3 * CTX_STAGE * 4;   // 76.8 KB
    cudaFuncSetAttribute(qkv_proj_kernel,
                         cudaFuncAttributeMaxDynamicSharedMemorySize, SC_SMEM);
    cudaFuncSetAttribute(gemm_cp_kernel,
                         cudaFuncAttributeMaxDynamicSharedMemorySize, SC_SMEM);
    cudaFuncSetAttribute(scores_mma_kernel,
                         cudaFuncAttributeMaxDynamicSharedMemorySize, SC_SMEM);
    cudaFuncSetAttribute(ctx_mma_kernel,
                         cudaFuncAttributeMaxDynamicSharedMemorySize, CTX_SMEM);

    const int M = BB * LL;

    cb_kernel<<<BB * SS, 256>>>(keys, Wcb, (float*)pcb);

    // fused q/k/v projections: one launch, z selects the GEMM
    dim3 gqkv(DK / 128, M / 128, 3);
    qkv_proj_kernel<<<gqkv, 256, SC_SMEM>>>(queries, keys, values,
                                            Wq, Wk, Wv, bv,
                                            (float*)pq, (float*)pk, (float*)pv);

    dim3 gsc(SS / 128, LL / 128, BB * HH);
    scores_mma_kernel<<<gsc, 256, SC_SMEM>>>((const float*)pq, (const float*)pk,
                                             mixing, (const float*)pcb,
                                             probs, (float*)ppsum);

    dim3 gctx(LL / 128, BB * HH);
    ctx_mma_kernel<<<gctx, 256, CTX_SMEM>>>(probs, (const float*)ppsum,
                                            (const float*)pv, (float*)pctx);

    dim3 gout(DOUT / 128, M / 128);
    gemm_cp_kernel<<<gout, 256, SC_SMEM>>>((const float*)pctx, Wd, bd, out, M, DOUT, DV);
}

// round 15
// speedup vs baseline: 1.0226x; 1.0226x over previous
#include <cuda_runtime.h>
#include <cuda_bf16.h>
#include <cstdint>

// Problem constants
#define BB   2
#define LL   2048
#define SS   2048
#define DIN  512
#define DK   512
#define DV   512
#define DOUT 512
#define HH   8
#define HD   64

#define OUT_ELEMS  ((long)BB * LL * DOUT)
#define PROB_ELEMS ((long)BB * HH * (long)LL * (long)SS)

// Scratch (device globals — no runtime allocation allowed)
__device__ float g_q  [BB * LL * DK];
__device__ float g_k  [BB * SS * DK];
__device__ float g_v  [BB * SS * DV];
__device__ float g_cb [BB * HH * SS];
__device__ float g_ctx[BB * LL * DV];
__device__ float g_psum[BB * HH * (long)LL * 16];   // stride 16, first 8 used
__device__ float g_probs[BB * HH * (long)LL * SS];

// ---------------------------------------------------------------------------
// tf32 helpers. f2tf32 = cvt.rna (unbiased round-to-nearest). Strategy: round
// at the PRODUCER (qkv/ctx epilogues) so consumer fragments are already tf32
// and the mma's HW truncation is the identity — keeps the issue-bound mma
// loops free of cvts (R12 measured +70us from fragment-side cvts).
// ---------------------------------------------------------------------------
__device__ __forceinline__ float f2tf32(float v) {
    uint32_t r;
    asm("cvt.rna.tf32.f32 %0, %1;" : "=r"(r) : "f"(v));
    return __uint_as_float(r);
}

__device__ __forceinline__ void mma_tf32(float& c0, float& c1, float& c2, float& c3,
                                         float a0, float a1, float a2, float a3,
                                         float b0, float b1) {
    asm volatile(
        "mma.sync.aligned.m16n8k8.row.col.f32.tf32.tf32.f32 "
        "{%0,%1,%2,%3}, {%4,%5,%6,%7}, {%8,%9}, {%0,%1,%2,%3};"
        : "+f"(c0), "+f"(c1), "+f"(c2), "+f"(c3)
        : "r"(__float_as_uint(a0)), "r"(__float_as_uint(a1)),
          "r"(__float_as_uint(a2)), "r"(__float_as_uint(a3)),
          "r"(__float_as_uint(b0)), "r"(__float_as_uint(b1)));
}

#define CP_ASYNC16(dst_u32, src) \
    asm volatile("cp.async.cg.shared.global [%0], [%1], 16;" :: "r"(dst_u32), "l"(src))
#define CP_COMMIT() asm volatile("cp.async.commit_group;" ::: "memory")
#define CP_WAIT2()  asm volatile("cp.async.wait_group 2;" ::: "memory")

// ---------------------------------------------------------------------------
// Fused q/k/v projection (z selects GEMM). Inputs raw fp32 -> RNA cvts at
// fragment load (unavoidable here); OUTPUTS pre-rounded to tf32 so all
// downstream consumers need no cvt.
// ---------------------------------------------------------------------------
__global__ __launch_bounds__(256, 2)
void qkv_proj_kernel(const float* __restrict__ q_in,
                     const float* __restrict__ k_in,
                     const float* __restrict__ v_in,
                     const float* __restrict__ Wq,
                     const float* __restrict__ Wk,
                     const float* __restrict__ Wv,
                     const float* __restrict__ bv,
                     float* __restrict__ q_out,
                     float* __restrict__ k_out,
                     float* __restrict__ v_out) {
    extern __shared__ float sm[];
    __shared__ float bias_s[128];

    const int tid  = threadIdx.x;
    const int wid  = tid >> 5;
    const int lane = tid & 31;
    const int warp_m = wid >> 2;
    const int warp_n = wid & 3;

    const int zz = blockIdx.z;
    const int bm = blockIdx.y * 128;
    const int bn = blockIdx.x * 128;
    const int K  = DIN, N = DK;

    const float* A; const float* W; float* C; bool hasb = false;
    if (zz == 0)      { A = q_in; W = Wq; C = q_out; }
    else if (zz == 1) { A = k_in; W = Wk; C = k_out; }
    else              { A = v_in; W = Wv; C = v_out; hasb = true; }

    const float* Ag = A + (size_t)bm * K;
    const float* Wg = W + (size_t)bn * K;

    if (tid < 128) bias_s[tid] = hasb ? bv[bn + tid] : 0.0f;

    const uint32_t sbase = (uint32_t)__cvta_generic_to_shared(sm);

    auto issue = [&](int cidx) {
        const uint32_t st_off = (uint32_t)(cidx % 3) * 8192u * 4u;
        const int kc = cidx * 32;
        #pragma unroll
        for (int i = 0; i < 4; i++) {
            int idx = tid + i * 256;
            int r   = idx >> 3;
            int gcf = (idx & 7) * 4;
            int sc  = gcf ^ ((r & 7) << 2);
            uint32_t da = sbase + st_off + (uint32_t)(r * 32 + sc) * 4u;
            CP_ASYNC16(da,          Ag + (size_t)r * K + kc + gcf);
            CP_ASYNC16(da + 16384u, Wg + (size_t)r * K + kc + gcf);
        }
    };

    float acc[4][4][4];
    #pragma unroll
    for (int i = 0; i < 4; i++)
        #pragma unroll
        for (int j = 0; j < 4; j++)
            #pragma unroll
            for (int t = 0; t < 4; t++) acc[i][j][t] = 0.0f;

    const int NC = K / 32;
    issue(0); CP_COMMIT();
    issue(1); CP_COMMIT();
    __syncthreads();

    const int ar = lane >> 2;
    const int ac = lane & 3;

    for (int c = 0; c < NC; c++) {
        if (c + 2 < NC) issue(c + 2);
        CP_COMMIT();
        CP_WAIT2();
        __syncthreads();

        const float* As = sm + (c % 3) * 8192;
        const float* Bs = As + 4096;

        #pragma unroll
        for (int kk = 0; kk < 4; kk++) {
            const int k0 = kk * 8;
            const int sc0 = (k0 + ac)     ^ (ar << 2);
            const int sc1 = (k0 + ac + 4) ^ (ar << 2);
            float a0[4], a1[4], a2[4], a3[4];
            #pragma unroll
            for (int i = 0; i < 4; i++) {
                int m = warp_m * 64 + i * 16;
                a0[i] = f2tf32(As[(m + ar    ) * 32 + sc0]);
                a1[i] = f2tf32(As[(m + ar + 8) * 32 + sc0]);
                a2[i] = f2tf32(As[(m + ar    ) * 32 + sc1]);
                a3[i] = f2tf32(As[(m + ar + 8) * 32 + sc1]);
            }
            float b0[4], b1[4];
            #pragma unroll
            for (int j = 0; j < 4; j++) {
                int n = warp_n * 32 + j * 8 + ar;
                b0[j] = f2tf32(Bs[n * 32 + sc0]);
                b1[j] = f2tf32(Bs[n * 32 + sc1]);
            }
            #pragma unroll
            for (int i = 0; i < 4; i++)
                #pragma unroll
                for (int j = 0; j < 4; j++)
                    mma_tf32(acc[i][j][0], acc[i][j][1], acc[i][j][2], acc[i][j][3],
                             a0[i], a1[i], a2[i], a3[i], b0[j], b1[j]);
        }
        __syncthreads();
    }

    // Epilogue: pre-round outputs to tf32 (consumers then need no cvt)
    #pragma unroll
    for (int i = 0; i < 4; i++) {
        int row = bm + warp_m * 64 + i * 16 + ar;
        #pragma unroll
        for (int j = 0; j < 4; j++) {
            int col = warp_n * 32 + j * 8 + ac * 2;
            float bb0 = bias_s[col], bb1 = bias_s[col + 1];
            float2 v0, v1;
            v0.x = f2tf32(acc[i][j][0] + bb0); v0.y = f2tf32(acc[i][j][1] + bb1);
            v1.x = f2tf32(acc[i][j][2] + bb0); v1.y = f2tf32(acc[i][j][3] + bb1);
            *(float2*)(C + (size_t)row * N + bn + col) = v0;
            *(float2*)(C + (size_t)(row + 8) * N + bn + col) = v1;
        }
    }
}

// ---------------------------------------------------------------------------
// Output GEMM: out = ctx @ Wd^T + bd. ctx is pre-rounded tf32 (no A cvt);
// Wd raw -> B fragments RNA-rounded.
// ---------------------------------------------------------------------------
__global__ __launch_bounds__(256, 2)
void gemm_cp_kernel(const float* __restrict__ A,
                    const float* __restrict__ W,
                    const float* __restrict__ bias,
                    float* __restrict__ C,
                    int M, int N, int K) {
    extern __shared__ float sm[];
    __shared__ float bias_s[128];

    const int tid  = threadIdx.x;
    const int wid  = tid >> 5;
    const int lane = tid & 31;
    const int warp_m = wid >> 2;
    const int warp_n = wid & 3;

    const int bm = blockIdx.y * 128;
    const int bn = blockIdx.x * 128;

    const float* Ag = A + (size_t)bm * K;
    const float* Wg = W + (size_t)bn * K;

    if (tid < 128) bias_s[tid] = bias[bn + tid];

    const uint32_t sbase = (uint32_t)__cvta_generic_to_shared(sm);

    auto issue = [&](int cidx) {
        const uint32_t st_off = (uint32_t)(cidx % 3) * 8192u * 4u;
        const int kc = cidx * 32;
        #pragma unroll
        for (int i = 0; i < 4; i++) {
            int idx = tid + i * 256;
            int r   = idx >> 3;
            int gcf = (idx & 7) * 4;
            int sc  = gcf ^ ((r & 7) << 2);
            uint32_t da = sbase + st_off + (uint32_t)(r * 32 + sc) * 4u;
            CP_ASYNC16(da,          Ag + (size_t)r * K + kc + gcf);
            CP_ASYNC16(da + 16384u, Wg + (size_t)r * K + kc + gcf);
        }
    };

    float acc[4][4][4];
    #pragma unroll
    for (int i = 0; i < 4; i++)
        #pragma unroll
        for (int j = 0; j < 4; j++)
            #pragma unroll
            for (int t = 0; t < 4; t++) acc[i][j][t] = 0.0f;

    const int NC = K / 32;
    issue(0); CP_COMMIT();
    issue(1); CP_COMMIT();
    __syncthreads();

    const int ar = lane >> 2;
    const int ac = lane & 3;

    for (int c = 0; c < NC; c++) {
        if (c + 2 < NC) issue(c + 2);
        CP_COMMIT();
        CP_WAIT2();
        __syncthreads();

        const float* As = sm + (c % 3) * 8192;
        const float* Bs = As + 4096;

        #pragma unroll
        for (int kk = 0; kk < 4; kk++) {
            const int k0 = kk * 8;
            const int sc0 = (k0 + ac)     ^ (ar << 2);
            const int sc1 = (k0 + ac + 4) ^ (ar << 2);
            float a0[4], a1[4], a2[4], a3[4];
            #pragma unroll
            for (int i = 0; i < 4; i++) {
                int m = warp_m * 64 + i * 16;
                a0[i] = As[(m + ar    ) * 32 + sc0];   // ctx pre-rounded tf32
                a1[i] = As[(m + ar + 8) * 32 + sc0];
                a2[i] = As[(m + ar    ) * 32 + sc1];
                a3[i] = As[(m + ar + 8) * 32 + sc1];
            }
            float b0[4], b1[4];
            #pragma unroll
            for (int j = 0; j < 4; j++) {
                int n = warp_n * 32 + j * 8 + ar;
                b0[j] = f2tf32(Bs[n * 32 + sc0]);
                b1[j] = f2tf32(Bs[n * 32 + sc1]);
            }
            #pragma unroll
            for (int i = 0; i < 4; i++)
                #pragma unroll
                for (int j = 0; j < 4; j++)
                    mma_tf32(acc[i][j][0], acc[i][j][1], acc[i][j][2], acc[i][j][3],
                             a0[i], a1[i], a2[i], a3[i], b0[j], b1[j]);
        }
        __syncthreads();
    }

    #pragma unroll
    for (int i = 0; i < 4; i++) {
        int row = bm + warp_m * 64 + i * 16 + ar;
        #pragma unroll
        for (int j = 0; j < 4; j++) {
            int col = warp_n * 32 + j * 8 + ac * 2;
            float bb0 = bias_s[col], bb1 = bias_s[col + 1];
            float2 v0, v1;
            v0.x = acc[i][j][0] + bb0; v0.y = acc[i][j][1] + bb1;
            v1.x = acc[i][j][2] + bb0; v1.y = acc[i][j][3] + bb1;
            *(float2*)(C + (size_t)row * N + bn + col) = v0;
            *(float2*)(C + (size_t)(row + 8) * N + bn + col) = v1;
        }
    }
}

// ---------------------------------------------------------------------------
// Scores: tf32 GEMM, CTA tile 128x256 (warp tile 64x64), cp.async 3-stage,
// BK=32, 1 CTA/SM. q is pre-rounded tf32 -> A fragments raw (no cvt/mul).
// mixing folded into B fragments: b = f2tf32(k * mix[k]) (8 mul + 8 cvt /kk).
//   e[z,l,s] = exp((score + cb) / 8) -> probs ; psum 8 partials per row.
// grid = (S/256, L/128, B*H), 256 threads, 144KB dynamic smem.
// ---------------------------------------------------------------------------
#define SC_STAGE 12288   // floats: A 128x32 (4096) + B 256x32 (8192)

__global__ __launch_bounds__(256, 1)
void scores_mma_kernel(const float* __restrict__ q,
                       const float* __restrict__ kmat,
                       const float* __restrict__ mixing,
                       const float* __restrict__ cb,
                       float* __restrict__ probs,
                       float* __restrict__ psum) {
    extern __shared__ float sm[];
    __shared__ float mix_s[DK];
    __shared__ float cb_s[256];
    __shared__ float rs[4][130];

    const int tid  = threadIdx.x;
    const int wid  = tid >> 5;
    const int lane = tid & 31;
    const int warp_m = wid >> 2;
    const int warp_n = wid & 3;

    const int z  = blockIdx.z;
    const int b  = z >> 3;
    const int h  = z & 7;
    const int bm = blockIdx.y * 128;
    const int bn = blockIdx.x * 256;

    const float* Aq = q    + (size_t)b * LL * DK + (size_t)bm * DK;
    const float* Bk = kmat + (size_t)b * SS * DK + (size_t)bn * DK;

    for (int i = tid; i < DK; i += 256) mix_s[i] = mixing[h * DK + i];
    cb_s[tid] = cb[(size_t)z * SS + bn + tid];

    const uint32_t sbase = (uint32_t)__cvta_generic_to_shared(sm);

    auto issue = [&](int cidx) {
        const uint32_t st_off = (uint32_t)(cidx % 3) * (SC_STAGE * 4u);
        const int kc = cidx * 32;
        #pragma unroll
        for (int i = 0; i < 4; i++) {               // A: 128x32
            int idx = tid + i * 256;
            int r   = idx >> 3;
            int gcf = (idx & 7) * 4;
            int sc  = gcf ^ ((r & 7) << 2);
            CP_ASYNC16(sbase + st_off + (uint32_t)(r * 32 + sc) * 4u,
                       Aq + (size_t)r * DK + kc + gcf);
        }
        #pragma unroll
        for (int i = 0; i < 8; i++) {               // B: 256x32
            int idx = tid + i * 256;
            int r   = idx >> 3;
            int gcf = (idx & 7) * 4;
            int sc  = gcf ^ ((r & 7) << 2);
            CP_ASYNC16(sbase + st_off + (uint32_t)(4096 + r * 32 + sc) * 4u,
                       Bk + (size_t)r * DK + kc + gcf);
        }
    };

    float acc[4][8][4];
    #pragma unroll
    for (int i = 0; i < 4; i++)
        #pragma unroll
        for (int j = 0; j < 8; j++)
            #pragma unroll
            for (int t = 0; t < 4; t++) acc[i][j][t] = 0.0f;

    const int NC = DK / 32;
    issue(0); CP_COMMIT();
    issue(1); CP_COMMIT();
    __syncthreads();

    const int ar = lane >> 2;
    const int ac = lane & 3;

    for (int c = 0; c < NC; c++) {
        if (c + 2 < NC) issue(c + 2);
        CP_COMMIT();
        CP_WAIT2();
        __syncthreads();

        const float* As = sm + (c % 3) * SC_STAGE;
        const float* Bs = As + 4096;
        const int kc = c * 32;

        #pragma unroll
        for (int kk = 0; kk < 4; kk++) {
            const int k0 = kk * 8;
            const int sc0 = (k0 + ac)     ^ (ar << 2);
            const int sc1 = (k0 + ac + 4) ^ (ar << 2);
            const float mv0 = mix_s[kc + k0 + ac];
            const float mv1 = mix_s[kc + k0 + ac + 4];
            float a0[4], a1[4], a2[4], a3[4];
            #pragma unroll
            for (int i = 0; i < 4; i++) {
                int m = warp_m * 64 + i * 16;
                a0[i] = As[(m + ar    ) * 32 + sc0];   // q pre-rounded tf32
                a1[i] = As[(m + ar + 8) * 32 + sc0];
                a2[i] = As[(m + ar    ) * 32 + sc1];
                a3[i] = As[(m + ar + 8) * 32 + sc1];
            }
            float b0[8], b1[8];
            #pragma unroll
            for (int j = 0; j < 8; j++) {
                int n = warp_n * 64 + j * 8 + ar;
                b0[j] = f2tf32(Bs[n * 32 + sc0] * mv0);
                b1[j] = f2tf32(Bs[n * 32 + sc1] * mv1);
            }
            #pragma unroll
            for (int i = 0; i < 4; i++)
                #pragma unroll
                for (int j = 0; j < 8; j++)
                    mma_tf32(acc[i][j][0], acc[i][j][1], acc[i][j][2], acc[i][j][3],
                             a0[i], a1[i], a2[i], a3[i], b0[j], b1[j]);
        }
        __syncthreads();
    }

    // Epilogue: e = exp((acc + cb)/8); streaming stores; per-row partials.
    const size_t rowbase = (size_t)z * LL;
    float rsum[4][2];
    #pragma unroll
    for (int i = 0; i < 4; i++) { rsum[i][0] = 0.0f; rsum[i][1] = 0.0f; }

    #pragma unroll
    for (int i = 0; i < 4; i++) {
        int row = bm + warp_m * 64 + i * 16 + ar;
        #pragma unroll
        for (int j = 0; j < 8; j++) {
            int col = warp_n * 64 + j * 8 + ac * 2;
            float cb0 = cb_s[col], cb1 = cb_s[col + 1];
            float2 v0, v1;
            v0.x = __expf((acc[i][j][0] + cb0) * 0.125f);
            v0.y = __expf((acc[i][j][1] + cb1) * 0.125f);
            v1.x = __expf((acc[i][j][2] + cb0) * 0.125f);
            v1.y = __expf((acc[i][j][3] + cb1) * 0.125f);
            rsum[i][0] += v0.x + v0.y;
            rsum[i][1] += v1.x + v1.y;
            __stcs((float2*)(probs + (rowbase + row    ) * SS + bn + col), v0);
            __stcs((float2*)(probs + (rowbase + row + 8) * SS + bn + col), v1);
        }
    }
    #pragma unroll
    for (int i = 0; i < 4; i++) {
        rsum[i][0] += __shfl_xor_sync(0xffffffffu, rsum[i][0], 1);
        rsum[i][0] += __shfl_xor_sync(0xffffffffu, rsum[i][0], 2);
        rsum[i][1] += __shfl_xor_sync(0xffffffffu, rsum[i][1], 1);
        rsum[i][1] += __shfl_xor_sync(0xffffffffu, rsum[i][1], 2);
    }
    if ((lane & 3) == 0) {
        #pragma unroll
        for (int i = 0; i < 4; i++) {
            int r = warp_m * 64 + i * 16 + ar;
            rs[warp_n][r]     = rsum[i][0];
            rs[warp_n][r + 8] = rsum[i][1];
        }
    }
    __syncthreads();
    if (tid < 128) {
        float s = rs[0][tid] + rs[1][tid] + rs[2][tid] + rs[3][tid];
        psum[(rowbase + bm + tid) * 16 + blockIdx.x] = s;   // blockIdx.x in 0..7
    }
}

// ---------------------------------------------------------------------------
// ctx via tf32 mma, cp.async 3-stage, BK=32. Normalization folded into the
// OUTPUT (exact commutation: ctx = inv * (e @ V)) — A fragments are
// f2tf32(raw e), B fragments raw (v pre-rounded tf32). Normalized probs
// written back in place (streaming). ctx stored pre-rounded to tf32.
// ---------------------------------------------------------------------------
#define CTX_STAGE 6400

__global__ __launch_bounds__(256, 2)
void ctx_mma_kernel(float* __restrict__ probs,
                    const float* __restrict__ psum,
                    const float* __restrict__ v,
                    float* __restrict__ ctx) {
    extern __shared__ float sm[];
    __shared__ float invs[128];

    const int tid  = threadIdx.x;
    const int wid  = tid >> 5;
    const int lane = tid & 31;
    const int warp_m = wid >> 2;
    const int warp_n = wid & 3;

    const int z  = blockIdx.y;
    const int b  = z >> 3;
    const int h  = z & 7;
    const int bm = blockIdx.x * 128;

    float* P = probs + ((size_t)z * LL + bm) * SS;
    const float* V = v + (size_t)b * SS * DV + h * HD;

    if (tid < 128) {
        const float* pp = psum + ((size_t)z * LL + bm + tid) * 16;
        float4 s0 = *(const float4*)(pp + 0);
        float4 s1 = *(const float4*)(pp + 4);
        float s = ((s0.x + s0.y) + (s0.z + s0.w)) + ((s1.x + s1.y) + (s1.z + s1.w));
        invs[tid] = 1.0f / s;
    }
    __syncthreads();

    const uint32_t sbase = (uint32_t)__cvta_generic_to_shared(sm);

    auto issue = [&](int cidx) {
        const uint32_t st = (uint32_t)(cidx % 3) * (CTX_STAGE * 4u);
        const int kc = cidx * 32;
        #pragma unroll
        for (int i = 0; i < 4; i++) {
            int idx = tid + i * 256;
            int r   = idx >> 3;
            int gcf = (idx & 7) * 4;
            int sc  = gcf ^ ((r & 7) << 2);
            CP_ASYNC16(sbase + st + (uint32_t)(r * 32 + sc) * 4u,
                       P + (size_t)r * SS + kc + gcf);
        }
        #pragma unroll
        for (int i = 0; i < 2; i++) {
            int idx = tid + i * 256;
            int vr  = idx >> 4;
            int vc  = (idx & 15) * 4;
            CP_ASYNC16(sbase + st + (uint32_t)(4096 + vr * 72 + vc) * 4u,
                       V + (size_t)(kc + vr) * DV + vc);
        }
    };

    const int ar = lane >> 2;
    const int ac = lane & 3;

    float ivR[8];   // output-row inverses
    #pragma unroll
    for (int i = 0; i < 4; i++) {
        ivR[2 * i]     = invs[warp_m * 64 + i * 16 + ar];
        ivR[2 * i + 1] = invs[warp_m * 64 + i * 16 + ar + 8];
    }
    float ivW[4];   // write-back row inverses
    #pragma unroll
    for (int i = 0; i < 4; i++) ivW[i] = invs[(tid + i * 256) >> 3];

    float acc[4][2][4];
    #pragma unroll
    for (int i = 0; i < 4; i++)
        #pragma unroll
        for (int j = 0; j < 2; j++)
            #pragma unroll
            for (int t = 0; t < 4; t++) acc[i][j][t] = 0.0f;

    const int NC = SS / 32;
    issue(0); CP_COMMIT();
    issue(1); CP_COMMIT();

    for (int c = 0; c < NC; c++) {
        if (c + 2 < NC) issue(c + 2);
        CP_COMMIT();
        CP_WAIT2();
        __syncthreads();

        const float* Ps = sm + (c % 3) * CTX_STAGE;
        const float* Vs = Ps + 4096;
        const int kc = c * 32;

        // normalized-probs write-back for this chunk (CTA-exclusive rows)
        #pragma unroll
        for (int i = 0; i < 4; i++) {
            int idx = tid + i * 256;
            int r   = idx >> 3;
            int gcf = (idx & 7) * 4;
            int sc  = gcf ^ ((r & 7) << 2);
            float4 e = *(const float4*)&Ps[r * 32 + sc];
            float iv = ivW[i];
            float4 nv = make_float4(e.x * iv, e.y * iv, e.z * iv, e.w * iv);
            __stcs((float4*)(P + (size_t)r * SS + kc + gcf), nv);
        }

        #pragma unroll
        for (int kk = 0; kk < 4; kk++) {
            const int k0 = kk * 8;
            const int sc0 = (k0 + ac)     ^ (ar << 2);
            const int sc1 = (k0 + ac + 4) ^ (ar << 2);
            float a0[4], a1[4], a2[4], a3[4];
            #pragma unroll
            for (int i = 0; i < 4; i++) {
                int m = warp_m * 64 + i * 16;
                a0[i] = f2tf32(Ps[(m + ar    ) * 32 + sc0]);
                a1[i] = f2tf32(Ps[(m + ar + 8) * 32 + sc0]);
                a2[i] = f2tf32(Ps[(m + ar    ) * 32 + sc1]);
                a3[i] = f2tf32(Ps[(m + ar + 8) * 32 + sc1]);
            }
            float b0[2], b1[2];
            #pragma unroll
            for (int j = 0; j < 2; j++) {
                int n = warp_n * 16 + j * 8 + ar;
                b0[j] = Vs[(k0 + ac) * 72 + n];        // v pre-rounded tf32
                b1[j] = Vs[(k0 + ac + 4) * 72 + n];
            }
            #pragma unroll
            for (int i = 0; i < 4; i++)
                #pragma unroll
                for (int j = 0; j < 2; j++)
                    mma_tf32(acc[i][j][0], acc[i][j][1], acc[i][j][2], acc[i][j][3],
                             a0[i], a1[i], a2[i], a3[i], b0[j], b1[j]);
        }
        __syncthreads();
    }

    // Epilogue: apply row inverse (exact commutation) + pre-round for out GEMM
    #pragma unroll
    for (int i = 0; i < 4; i++) {
        int row = bm + warp_m * 64 + i * 16 + ar;
        float iv0 = ivR[2 * i], iv1 = ivR[2 * i + 1];
        #pragma unroll
        for (int j = 0; j < 2; j++) {
            int col = warp_n * 16 + j * 8 + ac * 2;
            float2 v0, v1;
            v0.x = f2tf32(acc[i][j][0] * iv0); v0.y = f2tf32(acc[i][j][1] * iv0);
            v1.x = f2tf32(acc[i][j][2] * iv1); v1.y = f2tf32(acc[i][j][3] * iv1);
            *(float2*)(ctx + (size_t)(b * LL + row) * DV + h * HD + col) = v0;
            *(float2*)(ctx + (size_t)(b * LL + row + 8) * DV + h * HD + col) = v1;
        }
    }
}

// ---------------------------------------------------------------------------
// cb kernel (unchanged)
// ---------------------------------------------------------------------------
__global__ void cb_kernel(const float* __restrict__ keys,
                          const float* __restrict__ Wcb,
                          float* __restrict__ cb) {
    const int bs = blockIdx.x;
    const int b  = bs / SS;
    const int s  = bs % SS;
    __shared__ float krow[DIN];
    const int tid = threadIdx.x;
    for (int i = tid; i < DIN; i += 256) krow[i] = keys[(size_t)bs * DIN + i];
    __syncthreads();
    const int w    = tid >> 5;
    const int lane = tid & 31;
    float sum = 0.0f;
    #pragma unroll 4
    for (int i = lane; i < DIN; i += 32) sum += krow[i] * Wcb[w * DIN + i];
    #pragma unroll
    for (int o = 16; o > 0; o >>= 1) sum += __shfl_down_sync(0xffffffffu, sum, o);
    if (lane == 0) cb[(size_t)(b * HH + w) * SS + s] = sum;
}

// ---------------------------------------------------------------------------
extern "C" void kernel_launch(void* const* d_in, const int* in_sizes, int n_in,
                              void* d_out, int out_size) {
    const float* queries = (const float*)d_in[0];
    const float* keys    = (const float*)d_in[1];
    const float* values  = (const float*)d_in[2];
    const float* Wq      = (const float*)d_in[4];
    const float* Wk      = (const float*)d_in[5];
    const float* Wv      = (const float*)d_in[6];
    const float* bv      = (const float*)d_in[7];
    const float* Wcb     = (const float*)d_in[8];
    const float* mixing  = (const float*)d_in[9];
    const float* Wd      = (const float*)d_in[10];
    const float* bd      = (const float*)d_in[11];

    float* out = (float*)d_out;

    void *pq, *pk, *pv, *pcb, *pctx, *ppsum, *pprobs;
    cudaGetSymbolAddress(&pq,    g_q);
    cudaGetSymbolAddress(&pk,    g_k);
    cudaGetSymbolAddress(&pv,    g_v);
    cudaGetSymbolAddress(&pcb,   g_cb);
    cudaGetSymbolAddress(&pctx,  g_ctx);
    cudaGetSymbolAddress(&ppsum, g_psum);
    cudaGetSymbolAddress(&pprobs, g_probs);

    float* probs;
    if ((long)out_size >= OUT_ELEMS + PROB_ELEMS) probs = out + OUT_ELEMS;
    else                                           probs = (float*)pprobs;

    const int GP_SMEM  = 3 * 8192 * 4;        // 96 KB  (qkv / out GEMMs)
    const int SC_SMEM  = 3 * SC_STAGE * 4;    // 144 KB (scores)
    const int CTX_SMEM = 3 * CTX_STAGE * 4;   // 76.8 KB
    cudaFuncSetAttribute(qkv_proj_kernel,
                         cudaFuncAttributeMaxDynamicSharedMemorySize, GP_SMEM);
    cudaFuncSetAttribute(gemm_cp_kernel,
                         cudaFuncAttributeMaxDynamicSharedMemorySize, GP_SMEM);
    cudaFuncSetAttribute(scores_mma_kernel,
                         cudaFuncAttributeMaxDynamicSharedMemorySize, SC_SMEM);
    cudaFuncSetAttribute(ctx_mma_kernel,
                         cudaFuncAttributeMaxDynamicSharedMemorySize, CTX_SMEM);

    const int M = BB * LL;

    cb_kernel<<<BB * SS, 256>>>(keys, Wcb, (float*)pcb);

    dim3 gqkv(DK / 128, M / 128, 3);
    qkv_proj_kernel<<<gqkv, 256, GP_SMEM>>>(queries, keys, values,
                                            Wq, Wk, Wv, bv,
                                            (float*)pq, (float*)pk, (float*)pv);

    dim3 gsc(SS / 256, LL / 128, BB * HH);
    scores_mma_kernel<<<gsc, 256, SC_SMEM>>>((const float*)pq, (const float*)pk,
                                             mixing, (const float*)pcb,
                                             probs, (float*)ppsum);

    dim3 gctx(LL / 128, BB * HH);
    ctx_mma_kernel<<<gctx, 256, CTX_SMEM>>>(probs, (const float*)ppsum,
                                            (const float*)pv, (float*)pctx);

    dim3 gout(DOUT / 128, M / 128);
    gemm_cp_kernel<<<gout, 256, GP_SMEM>>>((const float*)pctx, Wd, bd, out, M, DOUT, DV);
}

// round 17
// speedup vs baseline: 1.1001x; 1.0758x over previous
#include <cuda_runtime.h>
#include <cuda_bf16.h>
#include <cstdint>

// Problem constants
#define BB   2
#define LL   2048
#define SS   2048
#define DIN  512
#define DK   512
#define DV   512
#define DOUT 512
#define HH   8
#define HD   64

#define OUT_ELEMS  ((long)BB * LL * DOUT)
#define PROB_ELEMS ((long)BB * HH * (long)LL * (long)SS)

// Scratch (device globals — no runtime allocation allowed)
__device__ float g_q  [BB * LL * DK];
__device__ float g_k  [BB * SS * DK];
__device__ float g_v  [BB * SS * DV];
__device__ float g_cb [BB * HH * SS];
__device__ float g_ctx[BB * LL * DV];
__device__ float g_psum[BB * HH * (long)LL * 16];
__device__ float g_probs[BB * HH * (long)LL * SS];

// ---------------------------------------------------------------------------
// tf32 helpers. f2tf32 = cvt.rna (unbiased). Strategy: round at PRODUCERS
// (qkv epilogue -> q/k/v are tf32; scores epilogue -> e is tf32; ctx epilogue
// -> ctx is tf32) so consumer fragments feed the mma raw and HW truncation is
// the identity. Keeps issue-bound mma loops nearly cvt-free (R12: fragment
// cvts cost +70us) while preserving unbiased rounding everywhere.
// ---------------------------------------------------------------------------
__device__ __forceinline__ float f2tf32(float v) {
    uint32_t r;
    asm("cvt.rna.tf32.f32 %0, %1;" : "=r"(r) : "f"(v));
    return __uint_as_float(r);
}

__device__ __forceinline__ void mma_tf32(float& c0, float& c1, float& c2, float& c3,
                                         float a0, float a1, float a2, float a3,
                                         float b0, float b1) {
    asm volatile(
        "mma.sync.aligned.m16n8k8.row.col.f32.tf32.tf32.f32 "
        "{%0,%1,%2,%3}, {%4,%5,%6,%7}, {%8,%9}, {%0,%1,%2,%3};"
        : "+f"(c0), "+f"(c1), "+f"(c2), "+f"(c3)
        : "r"(__float_as_uint(a0)), "r"(__float_as_uint(a1)),
          "r"(__float_as_uint(a2)), "r"(__float_as_uint(a3)),
          "r"(__float_as_uint(b0)), "r"(__float_as_uint(b1)));
}

#define CP_ASYNC16(dst_u32, src) \
    asm volatile("cp.async.cg.shared.global [%0], [%1], 16;" :: "r"(dst_u32), "l"(src))
#define CP_COMMIT() asm volatile("cp.async.commit_group;" ::: "memory")
#define CP_WAIT2()  asm volatile("cp.async.wait_group 2;" ::: "memory")

// ---------------------------------------------------------------------------
// Fused q/k/v projection (z selects GEMM). Inputs raw fp32 -> RNA cvts at
// fragment load; outputs pre-rounded tf32.
// ---------------------------------------------------------------------------
__global__ __launch_bounds__(256, 2)
void qkv_proj_kernel(const float* __restrict__ q_in,
                     const float* __restrict__ k_in,
                     const float* __restrict__ v_in,
                     const float* __restrict__ Wq,
                     const float* __restrict__ Wk,
                     const float* __restrict__ Wv,
                     const float* __restrict__ bv,
                     float* __restrict__ q_out,
                     float* __restrict__ k_out,
                     float* __restrict__ v_out) {
    extern __shared__ float sm[];
    __shared__ float bias_s[128];

    const int tid  = threadIdx.x;
    const int wid  = tid >> 5;
    const int lane = tid & 31;
    const int warp_m = wid >> 2;
    const int warp_n = wid & 3;

    const int zz = blockIdx.z;
    const int bm = blockIdx.y * 128;
    const int bn = blockIdx.x * 128;
    const int K  = DIN, N = DK;

    const float* A; const float* W; float* C; bool hasb = false;
    if (zz == 0)      { A = q_in; W = Wq; C = q_out; }
    else if (zz == 1) { A = k_in; W = Wk; C = k_out; }
    else              { A = v_in; W = Wv; C = v_out; hasb = true; }

    const float* Ag = A + (size_t)bm * K;
    const float* Wg = W + (size_t)bn * K;

    if (tid < 128) bias_s[tid] = hasb ? bv[bn + tid] : 0.0f;

    const uint32_t sbase = (uint32_t)__cvta_generic_to_shared(sm);

    auto issue = [&](int cidx) {
        const uint32_t st_off = (uint32_t)(cidx % 3) * 8192u * 4u;
        const int kc = cidx * 32;
        #pragma unroll
        for (int i = 0; i < 4; i++) {
            int idx = tid + i * 256;
            int r   = idx >> 3;
            int gcf = (idx & 7) * 4;
            int sc  = gcf ^ ((r & 7) << 2);
            uint32_t da = sbase + st_off + (uint32_t)(r * 32 + sc) * 4u;
            CP_ASYNC16(da,          Ag + (size_t)r * K + kc + gcf);
            CP_ASYNC16(da + 16384u, Wg + (size_t)r * K + kc + gcf);
        }
    };

    float acc[4][4][4];
    #pragma unroll
    for (int i = 0; i < 4; i++)
        #pragma unroll
        for (int j = 0; j < 4; j++)
            #pragma unroll
            for (int t = 0; t < 4; t++) acc[i][j][t] = 0.0f;

    const int NC = K / 32;
    issue(0); CP_COMMIT();
    issue(1); CP_COMMIT();
    __syncthreads();

    const int ar = lane >> 2;
    const int ac = lane & 3;

    for (int c = 0; c < NC; c++) {
        if (c + 2 < NC) issue(c + 2);
        CP_COMMIT();
        CP_WAIT2();
        __syncthreads();

        const float* As = sm + (c % 3) * 8192;
        const float* Bs = As + 4096;

        #pragma unroll
        for (int kk = 0; kk < 4; kk++) {
            const int k0 = kk * 8;
            const int sc0 = (k0 + ac)     ^ (ar << 2);
            const int sc1 = (k0 + ac + 4) ^ (ar << 2);
            float a0[4], a1[4], a2[4], a3[4];
            #pragma unroll
            for (int i = 0; i < 4; i++) {
                int m = warp_m * 64 + i * 16;
                a0[i] = f2tf32(As[(m + ar    ) * 32 + sc0]);
                a1[i] = f2tf32(As[(m + ar + 8) * 32 + sc0]);
                a2[i] = f2tf32(As[(m + ar    ) * 32 + sc1]);
                a3[i] = f2tf32(As[(m + ar + 8) * 32 + sc1]);
            }
            float b0[4], b1[4];
            #pragma unroll
            for (int j = 0; j < 4; j++) {
                int n = warp_n * 32 + j * 8 + ar;
                b0[j] = f2tf32(Bs[n * 32 + sc0]);
                b1[j] = f2tf32(Bs[n * 32 + sc1]);
            }
            #pragma unroll
            for (int i = 0; i < 4; i++)
                #pragma unroll
                for (int j = 0; j < 4; j++)
                    mma_tf32(acc[i][j][0], acc[i][j][1], acc[i][j][2], acc[i][j][3],
                             a0[i], a1[i], a2[i], a3[i], b0[j], b1[j]);
        }
        __syncthreads();
    }

    #pragma unroll
    for (int i = 0; i < 4; i++) {
        int row = bm + warp_m * 64 + i * 16 + ar;
        #pragma unroll
        for (int j = 0; j < 4; j++) {
            int col = warp_n * 32 + j * 8 + ac * 2;
            float bb0 = bias_s[col], bb1 = bias_s[col + 1];
            float2 v0, v1;
            v0.x = f2tf32(acc[i][j][0] + bb0); v0.y = f2tf32(acc[i][j][1] + bb1);
            v1.x = f2tf32(acc[i][j][2] + bb0); v1.y = f2tf32(acc[i][j][3] + bb1);
            *(float2*)(C + (size_t)row * N + bn + col) = v0;
            *(float2*)(C + (size_t)(row + 8) * N + bn + col) = v1;
        }
    }
}

// ---------------------------------------------------------------------------
// Output GEMM: out = ctx @ Wd^T + bd. ctx pre-rounded tf32 (A raw);
// Wd raw -> B fragments RNA-rounded.
// ---------------------------------------------------------------------------
__global__ __launch_bounds__(256, 2)
void gemm_cp_kernel(const float* __restrict__ A,
                    const float* __restrict__ W,
                    const float* __restrict__ bias,
                    float* __restrict__ C,
                    int M, int N, int K) {
    extern __shared__ float sm[];
    __shared__ float bias_s[128];

    const int tid  = threadIdx.x;
    const int wid  = tid >> 5;
    const int lane = tid & 31;
    const int warp_m = wid >> 2;
    const int warp_n = wid & 3;

    const int bm = blockIdx.y * 128;
    const int bn = blockIdx.x * 128;

    const float* Ag = A + (size_t)bm * K;
    const float* Wg = W + (size_t)bn * K;

    if (tid < 128) bias_s[tid] = bias[bn + tid];

    const uint32_t sbase = (uint32_t)__cvta_generic_to_shared(sm);

    auto issue = [&](int cidx) {
        const uint32_t st_off = (uint32_t)(cidx % 3) * 8192u * 4u;
        const int kc = cidx * 32;
        #pragma unroll
        for (int i = 0; i < 4; i++) {
            int idx = tid + i * 256;
            int r   = idx >> 3;
            int gcf = (idx & 7) * 4;
            int sc  = gcf ^ ((r & 7) << 2);
            uint32_t da = sbase + st_off + (uint32_t)(r * 32 + sc) * 4u;
            CP_ASYNC16(da,          Ag + (size_t)r * K + kc + gcf);
            CP_ASYNC16(da + 16384u, Wg + (size_t)r * K + kc + gcf);
        }
    };

    float acc[4][4][4];
    #pragma unroll
    for (int i = 0; i < 4; i++)
        #pragma unroll
        for (int j = 0; j < 4; j++)
            #pragma unroll
            for (int t = 0; t < 4; t++) acc[i][j][t] = 0.0f;

    const int NC = K / 32;
    issue(0); CP_COMMIT();
    issue(1); CP_COMMIT();
    __syncthreads();

    const int ar = lane >> 2;
    const int ac = lane & 3;

    for (int c = 0; c < NC; c++) {
        if (c + 2 < NC) issue(c + 2);
        CP_COMMIT();
        CP_WAIT2();
        __syncthreads();

        const float* As = sm + (c % 3) * 8192;
        const float* Bs = As + 4096;

        #pragma unroll
        for (int kk = 0; kk < 4; kk++) {
            const int k0 = kk * 8;
            const int sc0 = (k0 + ac)     ^ (ar << 2);
            const int sc1 = (k0 + ac + 4) ^ (ar << 2);
            float a0[4], a1[4], a2[4], a3[4];
            #pragma unroll
            for (int i = 0; i < 4; i++) {
                int m = warp_m * 64 + i * 16;
                a0[i] = As[(m + ar    ) * 32 + sc0];   // ctx pre-rounded tf32
                a1[i] = As[(m + ar + 8) * 32 + sc0];
                a2[i] = As[(m + ar    ) * 32 + sc1];
                a3[i] = As[(m + ar + 8) * 32 + sc1];
            }
            float b0[4], b1[4];
            #pragma unroll
            for (int j = 0; j < 4; j++) {
                int n = warp_n * 32 + j * 8 + ar;
                b0[j] = f2tf32(Bs[n * 32 + sc0]);
                b1[j] = f2tf32(Bs[n * 32 + sc1]);
            }
            #pragma unroll
            for (int i = 0; i < 4; i++)
                #pragma unroll
                for (int j = 0; j < 4; j++)
                    mma_tf32(acc[i][j][0], acc[i][j][1], acc[i][j][2], acc[i][j][3],
                             a0[i], a1[i], a2[i], a3[i], b0[j], b1[j]);
        }
        __syncthreads();
    }

    #pragma unroll
    for (int i = 0; i < 4; i++) {
        int row = bm + warp_m * 64 + i * 16 + ar;
        #pragma unroll
        for (int j = 0; j < 4; j++) {
            int col = warp_n * 32 + j * 8 + ac * 2;
            float bb0 = bias_s[col], bb1 = bias_s[col + 1];
            float2 v0, v1;
            v0.x = acc[i][j][0] + bb0; v0.y = acc[i][j][1] + bb1;
            v1.x = acc[i][j][2] + bb0; v1.y = acc[i][j][3] + bb1;
            *(float2*)(C + (size_t)row * N + bn + col) = v0;
            *(float2*)(C + (size_t)(row + 8) * N + bn + col) = v1;
        }
    }
}

// ---------------------------------------------------------------------------
// Scores: tf32 GEMM, CTA tile 128x128 (2 CTA/SM — proven fastest shape),
// cp.async 3-stage, BK=32. A fragments raw (q pre-rounded tf32);
// mixing folded into B: b = f2tf32(k * mix[k]). Per-kk issue count matches
// the fast R10 loop (64) but with unbiased rounding.
// Epilogue: e = f2tf32(exp((score+cb)/8)) -> probs pre-rounded so the ctx
// kernel's A fragments are also cvt-free. psum = 16 partials per row.
// grid = (S/128, L/128, B*H), 256 threads, 96KB dynamic smem.
// ---------------------------------------------------------------------------
__global__ __launch_bounds__(256, 2)
void scores_mma_kernel(const float* __restrict__ q,
                       const float* __restrict__ kmat,
                       const float* __restrict__ mixing,
                       const float* __restrict__ cb,
                       float* __restrict__ probs,
                       float* __restrict__ psum) {
    extern __shared__ float sm[];
    __shared__ float mix_s[DK];
    __shared__ float cb_s[128];
    __shared__ float rs[4][130];

    const int tid  = threadIdx.x;
    const int wid  = tid >> 5;
    const int lane = tid & 31;
    const int warp_m = wid >> 2;
    const int warp_n = wid & 3;

    const int z  = blockIdx.z;
    const int b  = z >> 3;
    const int h  = z & 7;
    const int bm = blockIdx.y * 128;
    const int bn = blockIdx.x * 128;

    const float* Aq = q    + (size_t)b * LL * DK + (size_t)bm * DK;
    const float* Bk = kmat + (size_t)b * SS * DK + (size_t)bn * DK;

    for (int i = tid; i < DK; i += 256) mix_s[i] = mixing[h * DK + i];
    if (tid < 128) cb_s[tid] = cb[(size_t)z * SS + bn + tid];

    const uint32_t sbase = (uint32_t)__cvta_generic_to_shared(sm);

    auto issue = [&](int cidx) {
        const uint32_t st_off = (uint32_t)(cidx % 3) * 8192u * 4u;
        const int kc = cidx * 32;
        #pragma unroll
        for (int i = 0; i < 4; i++) {
            int idx = tid + i * 256;
            int r   = idx >> 3;
            int gcf = (idx & 7) * 4;
            int sc  = gcf ^ ((r & 7) << 2);
            uint32_t da = sbase + st_off + (uint32_t)(r * 32 + sc) * 4u;
            CP_ASYNC16(da,          Aq + (size_t)r * DK + kc + gcf);
            CP_ASYNC16(da + 16384u, Bk + (size_t)r * DK + kc + gcf);
        }
    };

    float acc[4][4][4];
    #pragma unroll
    for (int i = 0; i < 4; i++)
        #pragma unroll
        for (int j = 0; j < 4; j++)
            #pragma unroll
            for (int t = 0; t < 4; t++) acc[i][j][t] = 0.0f;

    const int NC = DK / 32;
    issue(0); CP_COMMIT();
    issue(1); CP_COMMIT();
    __syncthreads();   // mix_s/cb_s visible

    const int ar = lane >> 2;
    const int ac = lane & 3;

    for (int c = 0; c < NC; c++) {
        if (c + 2 < NC) issue(c + 2);
        CP_COMMIT();
        CP_WAIT2();
        __syncthreads();

        const float* As = sm + (c % 3) * 8192;
        const float* Bs = As + 4096;
        const int kc = c * 32;

        #pragma unroll
        for (int kk = 0; kk < 4; kk++) {
            const int k0 = kk * 8;
            const int sc0 = (k0 + ac)     ^ (ar << 2);
            const int sc1 = (k0 + ac + 4) ^ (ar << 2);
            const float mv0 = mix_s[kc + k0 + ac];
            const float mv1 = mix_s[kc + k0 + ac + 4];
            float a0[4], a1[4], a2[4], a3[4];
            #pragma unroll
            for (int i = 0; i < 4; i++) {
                int m = warp_m * 64 + i * 16;
                a0[i] = As[(m + ar    ) * 32 + sc0];   // q pre-rounded tf32
                a1[i] = As[(m + ar + 8) * 32 + sc0];
                a2[i] = As[(m + ar    ) * 32 + sc1];
                a3[i] = As[(m + ar + 8) * 32 + sc1];
            }
            float b0[4], b1[4];
            #pragma unroll
            for (int j = 0; j < 4; j++) {
                int n = warp_n * 32 + j * 8 + ar;
                b0[j] = f2tf32(Bs[n * 32 + sc0] * mv0);
                b1[j] = f2tf32(Bs[n * 32 + sc1] * mv1);
            }
            #pragma unroll
            for (int i = 0; i < 4; i++)
                #pragma unroll
                for (int j = 0; j < 4; j++)
                    mma_tf32(acc[i][j][0], acc[i][j][1], acc[i][j][2], acc[i][j][3],
                             a0[i], a1[i], a2[i], a3[i], b0[j], b1[j]);
        }
        __syncthreads();
    }

    // Epilogue: e = f2tf32(exp((acc + cb)/8)) — pre-rounded so ctx A is raw.
    // rsum over the ROUNDED values keeps normalized rows summing to 1.
    const size_t rowbase = (size_t)z * LL;
    float rsum[4][2];
    #pragma unroll
    for (int i = 0; i < 4; i++) { rsum[i][0] = 0.0f; rsum[i][1] = 0.0f; }

    #pragma unroll
    for (int i = 0; i < 4; i++) {
        int row = bm + warp_m * 64 + i * 16 + ar;
        #pragma unroll
        for (int j = 0; j < 4; j++) {
            int col = warp_n * 32 + j * 8 + ac * 2;
            float cb0 = cb_s[col], cb1 = cb_s[col + 1];
            float2 v0, v1;
            v0.x = f2tf32(__expf((acc[i][j][0] + cb0) * 0.125f));
            v0.y = f2tf32(__expf((acc[i][j][1] + cb1) * 0.125f));
            v1.x = f2tf32(__expf((acc[i][j][2] + cb0) * 0.125f));
            v1.y = f2tf32(__expf((acc[i][j][3] + cb1) * 0.125f));
            rsum[i][0] += v0.x + v0.y;
            rsum[i][1] += v1.x + v1.y;
            __stcs((float2*)(probs + (rowbase + row    ) * SS + bn + col), v0);
            __stcs((float2*)(probs + (rowbase + row + 8) * SS + bn + col), v1);
        }
    }
    #pragma unroll
    for (int i = 0; i < 4; i++) {
        rsum[i][0] += __shfl_xor_sync(0xffffffffu, rsum[i][0], 1);
        rsum[i][0] += __shfl_xor_sync(0xffffffffu, rsum[i][0], 2);
        rsum[i][1] += __shfl_xor_sync(0xffffffffu, rsum[i][1], 1);
        rsum[i][1] += __shfl_xor_sync(0xffffffffu, rsum[i][1], 2);
    }
    if ((lane & 3) == 0) {
        #pragma unroll
        for (int i = 0; i < 4; i++) {
            int r = warp_m * 64 + i * 16 + ar;
            rs[warp_n][r]     = rsum[i][0];
            rs[warp_n][r + 8] = rsum[i][1];
        }
    }
    __syncthreads();
    if (tid < 128) {
        float s = rs[0][tid] + rs[1][tid] + rs[2][tid] + rs[3][tid];
        psum[(rowbase + bm + tid) * 16 + blockIdx.x] = s;   // 0..15
    }
}

// ---------------------------------------------------------------------------
// ctx via tf32 mma, cp.async 3-stage, BK=32. e pre-rounded tf32 -> A raw;
// v pre-rounded tf32 -> B raw. Normalization on the OUTPUT (exact
// commutation). Normalized probs write-back streaming. ctx stored tf32.
// ---------------------------------------------------------------------------
#define CTX_STAGE 6400

__global__ __launch_bounds__(256, 2)
void ctx_mma_kernel(float* __restrict__ probs,
                    const float* __restrict__ psum,
                    const float* __restrict__ v,
                    float* __restrict__ ctx) {
    extern __shared__ float sm[];
    __shared__ float invs[128];

    const int tid  = threadIdx.x;
    const int wid  = tid >> 5;
    const int lane = tid & 31;
    const int warp_m = wid >> 2;
    const int warp_n = wid & 3;

    const int z  = blockIdx.y;
    const int b  = z >> 3;
    const int h  = z & 7;
    const int bm = blockIdx.x * 128;

    float* P = probs + ((size_t)z * LL + bm) * SS;
    const float* V = v + (size_t)b * SS * DV + h * HD;

    if (tid < 128) {
        const float* pp = psum + ((size_t)z * LL + bm + tid) * 16;
        float4 s0 = *(const float4*)(pp + 0);
        float4 s1 = *(const float4*)(pp + 4);
        float4 s2 = *(const float4*)(pp + 8);
        float4 s3 = *(const float4*)(pp + 12);
        float s = ((s0.x + s0.y) + (s0.z + s0.w)) + ((s1.x + s1.y) + (s1.z + s1.w))
                + ((s2.x + s2.y) + (s2.z + s2.w)) + ((s3.x + s3.y) + (s3.z + s3.w));
        invs[tid] = 1.0f / s;
    }
    __syncthreads();

    const uint32_t sbase = (uint32_t)__cvta_generic_to_shared(sm);

    auto issue = [&](int cidx) {
        const uint32_t st = (uint32_t)(cidx % 3) * (CTX_STAGE * 4u);
        const int kc = cidx * 32;
        #pragma unroll
        for (int i = 0; i < 4; i++) {
            int idx = tid + i * 256;
            int r   = idx >> 3;
            int gcf = (idx & 7) * 4;
            int sc  = gcf ^ ((r & 7) << 2);
            CP_ASYNC16(sbase + st + (uint32_t)(r * 32 + sc) * 4u,
                       P + (size_t)r * SS + kc + gcf);
        }
        #pragma unroll
        for (int i = 0; i < 2; i++) {
            int idx = tid + i * 256;
            int vr  = idx >> 4;
            int vc  = (idx & 15) * 4;
            CP_ASYNC16(sbase + st + (uint32_t)(4096 + vr * 72 + vc) * 4u,
                       V + (size_t)(kc + vr) * DV + vc);
        }
    };

    const int ar = lane >> 2;
    const int ac = lane & 3;

    float ivR[8];
    #pragma unroll
    for (int i = 0; i < 4; i++) {
        ivR[2 * i]     = invs[warp_m * 64 + i * 16 + ar];
        ivR[2 * i + 1] = invs[warp_m * 64 + i * 16 + ar + 8];
    }
    float ivW[4];
    #pragma unroll
    for (int i = 0; i < 4; i++) ivW[i] = invs[(tid + i * 256) >> 3];

    float acc[4][2][4];
    #pragma unroll
    for (int i = 0; i < 4; i++)
        #pragma unroll
        for (int j = 0; j < 2; j++)
            #pragma unroll
            for (int t = 0; t < 4; t++) acc[i][j][t] = 0.0f;

    const int NC = SS / 32;
    issue(0); CP_COMMIT();
    issue(1); CP_COMMIT();

    for (int c = 0; c < NC; c++) {
        if (c + 2 < NC) issue(c + 2);
        CP_COMMIT();
        CP_WAIT2();
        __syncthreads();

        const float* Ps = sm + (c % 3) * CTX_STAGE;
        const float* Vs = Ps + 4096;
        const int kc = c * 32;

        // normalized-probs write-back for this chunk (CTA-exclusive rows)
        #pragma unroll
        for (int i = 0; i < 4; i++) {
            int idx = tid + i * 256;
            int r   = idx >> 3;
            int gcf = (idx & 7) * 4;
            int sc  = gcf ^ ((r & 7) << 2);
            float4 e = *(const float4*)&Ps[r * 32 + sc];
            float iv = ivW[i];
            float4 nv = make_float4(e.x * iv, e.y * iv, e.z * iv, e.w * iv);
            __stcs((float4*)(P + (size_t)r * SS + kc + gcf), nv);
        }

        #pragma unroll
        for (int kk = 0; kk < 4; kk++) {
            const int k0 = kk * 8;
            const int sc0 = (k0 + ac)     ^ (ar << 2);
            const int sc1 = (k0 + ac + 4) ^ (ar << 2);
            float a0[4], a1[4], a2[4], a3[4];
            #pragma unroll
            for (int i = 0; i < 4; i++) {
                int m = warp_m * 64 + i * 16;
                a0[i] = Ps[(m + ar    ) * 32 + sc0];   // e pre-rounded tf32
                a1[i] = Ps[(m + ar + 8) * 32 + sc0];
                a2[i] = Ps[(m + ar    ) * 32 + sc1];
                a3[i] = Ps[(m + ar + 8) * 32 + sc1];
            }
            float b0[2], b1[2];
            #pragma unroll
            for (int j = 0; j < 2; j++) {
                int n = warp_n * 16 + j * 8 + ar;
                b0[j] = Vs[(k0 + ac) * 72 + n];        // v pre-rounded tf32
                b1[j] = Vs[(k0 + ac + 4) * 72 + n];
            }
            #pragma unroll
            for (int i = 0; i < 4; i++)
                #pragma unroll
                for (int j = 0; j < 2; j++)
                    mma_tf32(acc[i][j][0], acc[i][j][1], acc[i][j][2], acc[i][j][3],
                             a0[i], a1[i], a2[i], a3[i], b0[j], b1[j]);
        }
        __syncthreads();
    }

    // Epilogue: row inverse (exact commutation) + pre-round for out GEMM
    #pragma unroll
    for (int i = 0; i < 4; i++) {
        int row = bm + warp_m * 64 + i * 16 + ar;
        float iv0 = ivR[2 * i], iv1 = ivR[2 * i + 1];
        #pragma unroll
        for (int j = 0; j < 2; j++) {
            int col = warp_n * 16 + j * 8 + ac * 2;
            float2 v0, v1;
            v0.x = f2tf32(acc[i][j][0] * iv0); v0.y = f2tf32(acc[i][j][1] * iv0);
            v1.x = f2tf32(acc[i][j][2] * iv1); v1.y = f2tf32(acc[i][j][3] * iv1);
            *(float2*)(ctx + (size_t)(b * LL + row) * DV + h * HD + col) = v0;
            *(float2*)(ctx + (size_t)(b * LL + row + 8) * DV + h * HD + col) = v1;
        }
    }
}

// ---------------------------------------------------------------------------
// cb kernel (unchanged)
// ---------------------------------------------------------------------------
__global__ void cb_kernel(const float* __restrict__ keys,
                          const float* __restrict__ Wcb,
                          float* __restrict__ cb) {
    const int bs = blockIdx.x;
    const int b  = bs / SS;
    const int s  = bs % SS;
    __shared__ float krow[DIN];
    const int tid = threadIdx.x;
    for (int i = tid; i < DIN; i += 256) krow[i] = keys[(size_t)bs * DIN + i];
    __syncthreads();
    const int w    = tid >> 5;
    const int lane = tid & 31;
    float sum = 0.0f;
    #pragma unroll 4
    for (int i = lane; i < DIN; i += 32) sum += krow[i] * Wcb[w * DIN + i];
    #pragma unroll
    for (int o = 16; o > 0; o >>= 1) sum += __shfl_down_sync(0xffffffffu, sum, o);
    if (lane == 0) cb[(size_t)(b * HH + w) * SS + s] = sum;
}

// ---------------------------------------------------------------------------
extern "C" void kernel_launch(void* const* d_in, const int* in_sizes, int n_in,
                              void* d_out, int out_size) {
    const float* queries = (const float*)d_in[0];
    const float* keys    = (const float*)d_in[1];
    const float* values  = (const float*)d_in[2];
    const float* Wq      = (const float*)d_in[4];
    const float* Wk      = (const float*)d_in[5];
    const float* Wv      = (const float*)d_in[6];
    const float* bv      = (const float*)d_in[7];
    const float* Wcb     = (const float*)d_in[8];
    const float* mixing  = (const float*)d_in[9];
    const float* Wd      = (const float*)d_in[10];
    const float* bd      = (const float*)d_in[11];

    float* out = (float*)d_out;

    void *pq, *pk, *pv, *pcb, *pctx, *ppsum, *pprobs;
    cudaGetSymbolAddress(&pq,    g_q);
    cudaGetSymbolAddress(&pk,    g_k);
    cudaGetSymbolAddress(&pv,    g_v);
    cudaGetSymbolAddress(&pcb,   g_cb);
    cudaGetSymbolAddress(&pctx,  g_ctx);
    cudaGetSymbolAddress(&ppsum, g_psum);
    cudaGetSymbolAddress(&pprobs, g_probs);

    float* probs;
    if ((long)out_size >= OUT_ELEMS + PROB_ELEMS) probs = out + OUT_ELEMS;
    else                                           probs = (float*)pprobs;

    const int GP_SMEM  = 3 * 8192 * 4;        // 96 KB (qkv / out / scores)
    const int CTX_SMEM = 3 * CTX_STAGE * 4;   // 76.8 KB
    cudaFuncSetAttribute(qkv_proj_kernel,
                         cudaFuncAttributeMaxDynamicSharedMemorySize, GP_SMEM);
    cudaFuncSetAttribute(gemm_cp_kernel,
                         cudaFuncAttributeMaxDynamicSharedMemorySize, GP_SMEM);
    cudaFuncSetAttribute(scores_mma_kernel,
                         cudaFuncAttributeMaxDynamicSharedMemorySize, GP_SMEM);
    cudaFuncSetAttribute(ctx_mma_kernel,
                         cudaFuncAttributeMaxDynamicSharedMemorySize, CTX_SMEM);

    const int M = BB * LL;

    cb_kernel<<<BB * SS, 256>>>(keys, Wcb, (float*)pcb);

    dim3 gqkv(DK / 128, M / 128, 3);
    qkv_proj_kernel<<<gqkv, 256, GP_SMEM>>>(queries, keys, values,
                                            Wq, Wk, Wv, bv,
                                            (float*)pq, (float*)pk, (float*)pv);

    dim3 gsc(SS / 128, LL / 128, BB * HH);
    scores_mma_kernel<<<gsc, 256, GP_SMEM>>>((const float*)pq, (const float*)pk,
                                             mixing, (const float*)pcb,
                                             probs, (float*)ppsum);

    dim3 gctx(LL / 128, BB * HH);
    ctx_mma_kernel<<<gctx, 256, CTX_SMEM>>>(probs, (const float*)ppsum,
                                            (const float*)pv, (float*)pctx);

    dim3 gout(DOUT / 128, M / 128);
    gemm_cp_kernel<<<gout, 256, GP_SMEM>>>((const float*)pctx, Wd, bd, out, M, DOUT, DV);
}